// round 4
// baseline (speedup 1.0000x reference)
#include <cuda_runtime.h>
#include <cuda_bf16.h>
#include <cstdint>

// Problem constants
#define EMBD   2048
#define HEADS  8
#define HDIM   256          // EMB / HEADS
#define BATCH  2
#define SEQ    2048
#define BN_ROWS (BATCH*SEQ)     // 4096
#define QKV_N  (3*EMBD)         // 6144
#define NBH    (BATCH*HEADS)    // 16

// Scratch (device globals — no runtime allocation allowed)
__device__ float g_q [(size_t)NBH * SEQ * HDIM];   //  33.5 MB  [bh][n][d]
__device__ float g_kT[(size_t)NBH * HDIM * SEQ];   //  33.5 MB  [bh][d][n]
__device__ float g_v [(size_t)NBH * SEQ * HDIM];   //  33.5 MB  [bh][n][d]
__device__ float g_s [(size_t)NBH * SEQ * SEQ];    // 268  MB  [bh][q][k]
__device__ float g_o [(size_t)BN_ROWS * EMBD];     //  33.5 MB  [b*n][h*d]

// ---------------------------------------------------------------------------
// Tiled SGEMM: 128x128 block tile, BK=8, 256 threads, 8x8 per thread.
// MODE 0: qkv   = x @ w_qkv + b_qkv, scatter to g_q / g_kT / g_v
// MODE 1: g_s   = Q @ K^T      (batched over z = bh, K^T prestaged as g_kT)
// MODE 2: g_o   = P @ V        (batched over z = bh, writes [b,n,h*d] layout)
// MODE 3: out   = g_o @ w_proj + b_proj
// All shapes divide the tile exactly — no bounds checks.
// ---------------------------------------------------------------------------
template <int MODE>
__global__ __launch_bounds__(256, 2)
void gemm_k(const float* __restrict__ Ain, const float* __restrict__ Bin,
            const float* __restrict__ bias, float* __restrict__ Cout)
{
    constexpr int K   = (MODE == 1) ? HDIM : ((MODE == 2) ? SEQ : EMBD);
    constexpr int N   = (MODE == 0) ? QKV_N : ((MODE == 1) ? SEQ :
                        (MODE == 2) ? HDIM : EMBD);
    constexpr int LDC = (MODE == 2) ? EMBD : N;

    const int z = blockIdx.z;

    const float* A;
    const float* B;
    float*       C = nullptr;
    if (MODE == 0) {
        A = Ain;  B = Bin;                           // scatter epilogue, C unused
    } else if (MODE == 1) {
        A = g_q  + (size_t)z * SEQ * HDIM;
        B = g_kT + (size_t)z * HDIM * SEQ;
        C = g_s  + (size_t)z * SEQ * SEQ;
    } else if (MODE == 2) {
        A = g_s  + (size_t)z * SEQ * SEQ;
        B = g_v  + (size_t)z * SEQ * HDIM;
        C = g_o  + (size_t)(z >> 3) * SEQ * EMBD + (size_t)(z & 7) * HDIM;
    } else {
        A = g_o;  B = Bin;  C = Cout;
    }

    __shared__ float As[8][128];
    __shared__ float Bs[8][128];

    const int tid      = threadIdx.x;
    const int rowBase  = (tid >> 4) << 3;      // 0..120
    const int colBase  = (tid & 15) << 3;      // 0..120
    const int blockRow = blockIdx.y * 128;
    const int blockCol = blockIdx.x * 128;

    // A staging: each thread loads one float4 of A (row = tid/2, col = (tid&1)*4)
    const int arow = tid >> 1;
    const int acol = (tid & 1) << 2;
    // B staging: each thread loads one float4 of B (row = tid/32, col = (tid&31)*4)
    const int brow = tid >> 5;
    const int bcol = (tid & 31) << 2;

    const float* Aptr = A + (size_t)(blockRow + arow) * K + acol;
    const float* Bptr = B + (size_t)brow * N + blockCol + bcol;

    float acc[8][8];
    #pragma unroll
    for (int i = 0; i < 8; i++)
        #pragma unroll
        for (int j = 0; j < 8; j++) acc[i][j] = 0.0f;

    // register prefetch of first tile
    float4 av = *(const float4*)Aptr;
    float4 bv = *(const float4*)Bptr;

    for (int k0 = 0; k0 < K; k0 += 8) {
        As[acol + 0][arow] = av.x;
        As[acol + 1][arow] = av.y;
        As[acol + 2][arow] = av.z;
        As[acol + 3][arow] = av.w;
        *(float4*)&Bs[brow][bcol] = bv;
        __syncthreads();

        if (k0 + 8 < K) {           // issue next tile's LDGs before compute
            Aptr += 8;
            Bptr += (size_t)8 * N;
            av = *(const float4*)Aptr;
            bv = *(const float4*)Bptr;
        }

        #pragma unroll
        for (int kk = 0; kk < 8; kk++) {
            float4 a0 = *(const float4*)&As[kk][rowBase];
            float4 a1 = *(const float4*)&As[kk][rowBase + 4];
            float4 b0 = *(const float4*)&Bs[kk][colBase];
            float4 b1 = *(const float4*)&Bs[kk][colBase + 4];
            float a[8] = {a0.x, a0.y, a0.z, a0.w, a1.x, a1.y, a1.z, a1.w};
            float b[8] = {b0.x, b0.y, b0.z, b0.w, b1.x, b1.y, b1.z, b1.w};
            #pragma unroll
            for (int i = 0; i < 8; i++)
                #pragma unroll
                for (int j = 0; j < 8; j++)
                    acc[i][j] = fmaf(a[i], b[j], acc[i][j]);
        }
        __syncthreads();
    }

    // ---------------- epilogue ----------------
    if (MODE == 0) {
        // qkv column j = (h*HDIM + d)*3 + which
        #pragma unroll
        for (int i = 0; i < 8; i++) {
            const int gi = blockRow + rowBase + i;
            const int bb = gi >> 11;            // / SEQ
            const int ni = gi & (SEQ - 1);
            #pragma unroll
            for (int j = 0; j < 8; j++) {
                const int gj    = blockCol + colBase + j;
                const float val = acc[i][j] + bias[gj];
                const int which = gj % 3;
                const int tt    = gj / 3;
                const int h     = tt >> 8;       // / HDIM
                const int d     = tt & (HDIM - 1);
                const int bh    = (bb << 3) + h;
                if (which == 0)
                    g_q[((size_t)bh * SEQ + ni) * HDIM + d] = val;
                else if (which == 1)
                    g_kT[((size_t)bh * HDIM + d) * SEQ + ni] = val;
                else
                    g_v[((size_t)bh * SEQ + ni) * HDIM + d] = val;
            }
        }
    } else {
        #pragma unroll
        for (int i = 0; i < 8; i++) {
            const int gi = blockRow + rowBase + i;
            float* crow = C + (size_t)gi * LDC + blockCol + colBase;
            #pragma unroll
            for (int j4 = 0; j4 < 8; j4 += 4) {
                float4 v;
                if (MODE == 3) {
                    const int gj = blockCol + colBase + j4;
                    v.x = acc[i][j4 + 0] + bias[gj + 0];
                    v.y = acc[i][j4 + 1] + bias[gj + 1];
                    v.z = acc[i][j4 + 2] + bias[gj + 2];
                    v.w = acc[i][j4 + 3] + bias[gj + 3];
                } else {
                    v.x = acc[i][j4 + 0];
                    v.y = acc[i][j4 + 1];
                    v.z = acc[i][j4 + 2];
                    v.w = acc[i][j4 + 3];
                }
                *(float4*)&crow[j4] = v;
            }
        }
    }
}

// ---------------------------------------------------------------------------
// Row softmax over g_s, fused with the post-softmax 1/sqrt(EMB) scaling.
// One block per row (256 threads, 8 values/thread, single read + single write).
// ---------------------------------------------------------------------------
__global__ __launch_bounds__(256)
void softmax_k()
{
    constexpr int   N         = SEQ;
    constexpr float INV_SCALE = 0.02209708691207961f;   // 1/sqrt(2048)

    float* p = g_s + (size_t)blockIdx.x * N;
    const int t = threadIdx.x;
    const int w = t >> 5;
    const int l = t & 31;

    float v[8];
    float m = -3.0e38f;
    #pragma unroll
    for (int u = 0; u < 8; u++) {
        v[u] = p[t + 256 * u];
        m = fmaxf(m, v[u]);
    }
    #pragma unroll
    for (int o = 16; o > 0; o >>= 1)
        m = fmaxf(m, __shfl_xor_sync(0xffffffffu, m, o));

    __shared__ float redm[8];
    __shared__ float reds[8];
    if (l == 0) redm[w] = m;
    __syncthreads();
    m = redm[0];
    #pragma unroll
    for (int i = 1; i < 8; i++) m = fmaxf(m, redm[i]);

    float s = 0.0f;
    #pragma unroll
    for (int u = 0; u < 8; u++) {
        v[u] = __expf(v[u] - m);
        s += v[u];
    }
    #pragma unroll
    for (int o = 16; o > 0; o >>= 1)
        s += __shfl_xor_sync(0xffffffffu, s, o);
    if (l == 0) reds[w] = s;
    __syncthreads();
    s = reds[0];
    #pragma unroll
    for (int i = 1; i < 8; i++) s += reds[i];

    const float r = INV_SCALE / s;
    #pragma unroll
    for (int u = 0; u < 8; u++)
        p[t + 256 * u] = v[u] * r;
}

// ---------------------------------------------------------------------------
extern "C" void kernel_launch(void* const* d_in, const int* in_sizes, int n_in,
                              void* d_out, int out_size)
{
    const float* x      = (const float*)d_in[0];
    const float* w_qkv  = (const float*)d_in[1];
    const float* b_qkv  = (const float*)d_in[2];
    const float* w_proj = (const float*)d_in[3];
    const float* b_proj = (const float*)d_in[4];
    float*       out    = (float*)d_out;

    // 1) QKV projection + de-interleave into Q / K^T / V
    gemm_k<0><<<dim3(QKV_N / 128, BN_ROWS / 128, 1), 256>>>(x, w_qkv, b_qkv, nullptr);
    // 2) scores S = Q @ K^T  (per bh)
    gemm_k<1><<<dim3(SEQ / 128, SEQ / 128, NBH), 256>>>(nullptr, nullptr, nullptr, nullptr);
    // 3) softmax rows (folds 1/sqrt(EMB))
    softmax_k<<<NBH * SEQ, 256>>>();
    // 4) O = P @ V, written in [b, n, h*d] layout
    gemm_k<2><<<dim3(HDIM / 128, SEQ / 128, NBH), 256>>>(nullptr, nullptr, nullptr, nullptr);
    // 5) final projection + bias
    gemm_k<3><<<dim3(EMBD / 128, BN_ROWS / 128, 1), 256>>>(nullptr, w_proj, b_proj, out);
}

// round 9
// speedup vs baseline: 1.2519x; 1.2519x over previous
#include <cuda_runtime.h>
#include <cstdint>

// ---------------------------------------------------------------------------
// Problem constants
// ---------------------------------------------------------------------------
#define EMBD   2048
#define HEADS  8
#define HDIM   256
#define BATCH  2
#define SEQ    2048
#define BN_ROWS (BATCH*SEQ)      // 4096
#define QKV_N  (3*EMBD)          // 6144
#define NBH    (BATCH*HEADS)     // 16

// ---------------------------------------------------------------------------
// Device scratch (no runtime allocation allowed)
// ---------------------------------------------------------------------------
__device__ __align__(1024) float g_wqkvT [(size_t)QKV_N  * EMBD];     // w_qkv^T  [6144][2048]
__device__ __align__(1024) float g_wprojT[(size_t)EMBD   * EMBD];     // w_proj^T [2048][2048]
__device__ __align__(1024) float g_q     [(size_t)NBH * SEQ  * HDIM]; // [bh][n][d]
__device__ __align__(1024) float g_k     [(size_t)NBH * SEQ  * HDIM]; // [bh][n][d]
__device__ __align__(1024) float g_vT    [(size_t)NBH * HDIM * SEQ ]; // [bh][d][n]
__device__ __align__(1024) float g_s     [(size_t)NBH * SEQ  * SEQ ]; // [bh][q][k]
__device__ __align__(1024) float g_o     [(size_t)BN_ROWS * EMBD];    // [b*n][h*d]

// ---------------------------------------------------------------------------
// Helpers
// ---------------------------------------------------------------------------
__device__ __forceinline__ void cp_async16(uint32_t s, const void* g) {
    asm volatile("cp.async.cg.shared.global [%0], [%1], 16;" :: "r"(s), "l"(g) : "memory");
}
#define CP_COMMIT() asm volatile("cp.async.commit_group;" ::: "memory")
#define CP_WAIT1()  asm volatile("cp.async.wait_group 1;" ::: "memory")

__device__ __forceinline__ uint32_t smem_u32(const void* p) {
    uint32_t a;
    asm("{ .reg .u64 t; cvta.to.shared.u64 t, %1; cvt.u32.u64 %0, t; }"
        : "=r"(a) : "l"(p));
    return a;
}

// Split fp32 into tf32 hi + tf32 lo (error-compensated tf32x3 operands)
__device__ __forceinline__ void split_tf32(float v, uint32_t& hi, uint32_t& lo) {
    uint32_t h;
    asm("cvt.rna.tf32.f32 %0, %1;" : "=r"(h) : "f"(v));
    float r = v - __uint_as_float(h);
    uint32_t l;
    asm("cvt.rna.tf32.f32 %0, %1;" : "=r"(l) : "f"(r));
    hi = h; lo = l;
}

// tf32 tensor-core mma: D(16x8) += A(16x8) * B(8x8), A row-major, B col-major
__device__ __forceinline__ void mma_tf32(float* c, const uint32_t* a, const uint32_t* b) {
    asm volatile(
        "mma.sync.aligned.m16n8k8.row.col.f32.tf32.tf32.f32 "
        "{%0,%1,%2,%3}, {%4,%5,%6,%7}, {%8,%9}, {%0,%1,%2,%3};"
        : "+f"(c[0]), "+f"(c[1]), "+f"(c[2]), "+f"(c[3])
        : "r"(a[0]), "r"(a[1]), "r"(a[2]), "r"(a[3]), "r"(b[0]), "r"(b[1]));
}

// ---------------------------------------------------------------------------
// tf32x3 HMMA GEMM: tile 128x128, BK=32, 3-stage cp.async, 8 warps (4x2),
// warp tile 32x64, mma m16n8k8 with hi/lo error compensation (3 MMAs/tile).
// A is [M][K] row-major, B is [N][K] row-major (i.e. B^T => col-major B).
// MODE 0: x @ wqkvT^T     -> scatter Q / K / V^T (+bias)
// MODE 1: Q @ K^T per bh  -> g_s
// MODE 2: P @ V per bh    -> g_o   ([b,n,h*d] layout)
// MODE 3: g_o @ wprojT^T  -> out (+bias)
// ---------------------------------------------------------------------------
#define BK       32
#define SROW     36                      // 32 + 4 pad floats
#define TILE_FLT (128 * SROW)            // per-operand floats per stage
#define STG_FLT  (2 * TILE_FLT)          // A + B
#define STAGES   3
#define SMEM_BYTES (STAGES * STG_FLT * 4)   // 110,592

template <int MODE>
__global__ __launch_bounds__(256, 1)
void tc_gemm(const float* __restrict__ Ain, const float* __restrict__ bias,
             float* __restrict__ Cout)
{
    constexpr int K     = (MODE == 1) ? HDIM : ((MODE == 2) ? SEQ : EMBD);
    constexpr int ITERS = K / BK;

    const int z  = blockIdx.z;
    const int m0 = blockIdx.y * 128;
    const int n0 = blockIdx.x * 128;

    const float* A; const float* B; float* C = nullptr; int ldc = 0;
    if (MODE == 0)      { A = Ain;                          B = g_wqkvT; }
    else if (MODE == 1) { A = g_q  + (size_t)z * SEQ * HDIM;
                          B = g_k  + (size_t)z * SEQ * HDIM;
                          C = g_s  + (size_t)z * SEQ * SEQ;  ldc = SEQ; }
    else if (MODE == 2) { A = g_s  + (size_t)z * SEQ * SEQ;
                          B = g_vT + (size_t)z * HDIM * SEQ;
                          C = g_o  + (size_t)(z >> 3) * SEQ * EMBD
                                   + (size_t)(z & 7) * HDIM; ldc = EMBD; }
    else                { A = g_o;  B = g_wprojT;  C = Cout; ldc = EMBD; }

    extern __shared__ __align__(128) float smem[];
    const uint32_t sb = smem_u32(smem);

    const int tid  = threadIdx.x;
    const int wid  = tid >> 5;
    const int lane = tid & 31;
    const int wm   = wid & 3;          // warp row  (4)  -> 32 rows
    const int wn   = wid >> 2;         // warp col  (2)  -> 64 cols
    const int grp  = lane >> 2;        // 0..7
    const int qid  = lane & 3;         // 0..3

    const char* Abase = (const char*)A + (size_t)m0 * K * 4;
    const char* Bbase = (const char*)B + (size_t)n0 * K * 4;

    auto issue = [&](int it, int s) {
        const uint32_t aS = sb + (uint32_t)(s * STG_FLT) * 4;
        const uint32_t bS = aS + (uint32_t)TILE_FLT * 4;
        const char* gA = Abase + (size_t)it * 128;     // BK floats = 128B
        const char* gB = Bbase + (size_t)it * 128;
        #pragma unroll
        for (int j = 0; j < 4; j++) {
            int u = tid + 256 * j;
            int r = u >> 3, i = u & 7;
            cp_async16(aS + (uint32_t)(r * SROW * 4 + i * 16), gA + (size_t)r * K * 4 + i * 16);
        }
        #pragma unroll
        for (int j = 0; j < 4; j++) {
            int u = tid + 256 * j;
            int r = u >> 3, i = u & 7;
            cp_async16(bS + (uint32_t)(r * SROW * 4 + i * 16), gB + (size_t)r * K * 4 + i * 16);
        }
        CP_COMMIT();
    };

    float acc[2][8][4];
    #pragma unroll
    for (int mt = 0; mt < 2; mt++)
        #pragma unroll
        for (int nt = 0; nt < 8; nt++)
            #pragma unroll
            for (int e = 0; e < 4; e++) acc[mt][nt][e] = 0.0f;

    issue(0, 0);
    issue(1, 1);

    for (int it = 0; it < ITERS; it++) {
        const int s = it % STAGES;
        CP_WAIT1();                 // stage 'it' data resident
        __syncthreads();            // everyone done with compute(it-1) too

        if (it + 2 < ITERS) issue(it + 2, (it + 2) % STAGES);
        else                CP_COMMIT();   // keep group accounting uniform

        const float* As = smem + s * STG_FLT;
        const float* Bs = As + TILE_FLT;
        const float* Aw = As + (wm * 32 + grp) * SROW + qid;   // row grp of warp tile
        const float* Bw = Bs + (wn * 64 + grp) * SROW + qid;

        #pragma unroll
        for (int ks = 0; ks < 4; ks++) {
            const int k0 = ks * 8;
            uint32_t ah[2][4], al[2][4], bh[8][2], bl[8][2];
            #pragma unroll
            for (int mt = 0; mt < 2; mt++) {
                const float* p = Aw + mt * 16 * SROW + k0;
                split_tf32(p[0],            ah[mt][0], al[mt][0]);
                split_tf32(p[8 * SROW],     ah[mt][1], al[mt][1]);
                split_tf32(p[4],            ah[mt][2], al[mt][2]);
                split_tf32(p[8 * SROW + 4], ah[mt][3], al[mt][3]);
            }
            #pragma unroll
            for (int nt = 0; nt < 8; nt++) {
                const float* p = Bw + nt * 8 * SROW + k0;
                split_tf32(p[0], bh[nt][0], bl[nt][0]);
                split_tf32(p[4], bh[nt][1], bl[nt][1]);
            }
            // tf32x3: hi*hi + hi*lo + lo*hi (lo*lo dropped, O(eps^2))
            #pragma unroll
            for (int mt = 0; mt < 2; mt++)
                #pragma unroll
                for (int nt = 0; nt < 8; nt++) {
                    mma_tf32(acc[mt][nt], ah[mt], bh[nt]);
                    mma_tf32(acc[mt][nt], ah[mt], bl[nt]);
                    mma_tf32(acc[mt][nt], al[mt], bh[nt]);
                }
        }
        __syncthreads();            // done reading stage s before it's refilled
    }

    // ---------------- epilogue ----------------
    #pragma unroll
    for (int mt = 0; mt < 2; mt++) {
        #pragma unroll
        for (int half = 0; half < 2; half++) {
            const int gi = m0 + wm * 32 + mt * 16 + grp + half * 8;
            if (MODE == 0) {
                const int bb = gi >> 11;            // batch
                const int ni = gi & (SEQ - 1);      // token
                #pragma unroll
                for (int nt = 0; nt < 8; nt++) {
                    #pragma unroll
                    for (int e = 0; e < 2; e++) {
                        const int gj = n0 + wn * 64 + nt * 8 + qid * 2 + e;
                        float val = acc[mt][nt][half * 2 + e] + bias[gj];
                        const int which = gj % 3;
                        const int tt    = gj / 3;
                        const int h     = tt >> 8;
                        const int d     = tt & (HDIM - 1);
                        const int bh    = (bb << 3) + h;
                        if (which == 0)
                            g_q [((size_t)bh * SEQ + ni) * HDIM + d] = val;
                        else if (which == 1)
                            g_k [((size_t)bh * SEQ + ni) * HDIM + d] = val;
                        else
                            g_vT[((size_t)bh * HDIM + d) * SEQ + ni] = val;
                    }
                }
            } else {
                float* crow = C + (size_t)gi * ldc + n0 + wn * 64 + qid * 2;
                #pragma unroll
                for (int nt = 0; nt < 8; nt++) {
                    float2 v;
                    v.x = acc[mt][nt][half * 2 + 0];
                    v.y = acc[mt][nt][half * 2 + 1];
                    if (MODE == 3) {
                        const int gj = n0 + wn * 64 + nt * 8 + qid * 2;
                        v.x += bias[gj + 0];
                        v.y += bias[gj + 1];
                    }
                    *(float2*)(crow + nt * 8) = v;
                }
            }
        }
    }
}

// ---------------------------------------------------------------------------
// Weight transpose (out[n][k] = in[k][n]), full fp32
// ---------------------------------------------------------------------------
__global__ __launch_bounds__(256)
void transpose_k(const float* __restrict__ in, float* __restrict__ out, int R, int C)
{
    __shared__ float t[32][33];
    const int bx = blockIdx.x * 32, by = blockIdx.y * 32;
    const int x = threadIdx.x & 31, y = threadIdx.x >> 5;   // 32 x 8
    #pragma unroll
    for (int j = 0; j < 32; j += 8)
        t[y + j][x] = in[(size_t)(by + y + j) * C + bx + x];
    __syncthreads();
    #pragma unroll
    for (int j = 0; j < 32; j += 8)
        out[(size_t)(bx + y + j) * R + by + x] = t[x][y + j];
}

// ---------------------------------------------------------------------------
// Row softmax over g_s with post-softmax 1/sqrt(EMB) folded in
// ---------------------------------------------------------------------------
__global__ __launch_bounds__(256)
void softmax_k()
{
    constexpr float INV_SCALE = 0.02209708691207961f;   // 1/sqrt(2048)
    float* p = g_s + (size_t)blockIdx.x * SEQ;
    const int t = threadIdx.x, w = t >> 5, l = t & 31;

    float v[8];
    float m = -3.0e38f;
    #pragma unroll
    for (int u = 0; u < 8; u++) { v[u] = p[t + 256 * u]; m = fmaxf(m, v[u]); }
    #pragma unroll
    for (int o = 16; o > 0; o >>= 1) m = fmaxf(m, __shfl_xor_sync(~0u, m, o));

    __shared__ float redm[8], reds[8];
    if (l == 0) redm[w] = m;
    __syncthreads();
    m = redm[0];
    #pragma unroll
    for (int i = 1; i < 8; i++) m = fmaxf(m, redm[i]);

    float s = 0.0f;
    #pragma unroll
    for (int u = 0; u < 8; u++) { v[u] = __expf(v[u] - m); s += v[u]; }
    #pragma unroll
    for (int o = 16; o > 0; o >>= 1) s += __shfl_xor_sync(~0u, s, o);
    if (l == 0) reds[w] = s;
    __syncthreads();
    s = reds[0];
    #pragma unroll
    for (int i = 1; i < 8; i++) s += reds[i];

    const float r = INV_SCALE / s;
    #pragma unroll
    for (int u = 0; u < 8; u++)
        p[t + 256 * u] = v[u] * r;
}

// ---------------------------------------------------------------------------
extern "C" void kernel_launch(void* const* d_in, const int* in_sizes, int n_in,
                              void* d_out, int out_size)
{
    const float* x      = (const float*)d_in[0];
    const float* w_qkv  = (const float*)d_in[1];
    const float* b_qkv  = (const float*)d_in[2];
    const float* w_proj = (const float*)d_in[3];
    const float* b_proj = (const float*)d_in[4];
    float*       out    = (float*)d_out;

    cudaFuncSetAttribute(tc_gemm<0>, cudaFuncAttributeMaxDynamicSharedMemorySize, SMEM_BYTES);
    cudaFuncSetAttribute(tc_gemm<1>, cudaFuncAttributeMaxDynamicSharedMemorySize, SMEM_BYTES);
    cudaFuncSetAttribute(tc_gemm<2>, cudaFuncAttributeMaxDynamicSharedMemorySize, SMEM_BYTES);
    cudaFuncSetAttribute(tc_gemm<3>, cudaFuncAttributeMaxDynamicSharedMemorySize, SMEM_BYTES);

    float* gwq; float* gwp;
    cudaGetSymbolAddress((void**)&gwq, g_wqkvT);
    cudaGetSymbolAddress((void**)&gwp, g_wprojT);

    // 0) weight transposes (B operands must be [N][K])
    transpose_k<<<dim3(QKV_N / 32, EMBD / 32), 256>>>(w_qkv,  gwq, EMBD, QKV_N);
    transpose_k<<<dim3(EMBD  / 32, EMBD / 32), 256>>>(w_proj, gwp, EMBD, EMBD);

    // 1) QKV projection + de-interleave (Q, K, V^T)
    tc_gemm<0><<<dim3(QKV_N / 128, BN_ROWS / 128, 1), 256, SMEM_BYTES>>>(x, b_qkv, nullptr);
    // 2) scores S = Q @ K^T per bh
    tc_gemm<1><<<dim3(SEQ / 128, SEQ / 128, NBH), 256, SMEM_BYTES>>>(nullptr, nullptr, nullptr);
    // 3) softmax (folds 1/sqrt(EMB))
    softmax_k<<<NBH * SEQ, 256>>>();
    // 4) O = P @ V per bh -> [b, n, h*d]
    tc_gemm<2><<<dim3(HDIM / 128, SEQ / 128, NBH), 256, SMEM_BYTES>>>(nullptr, nullptr, nullptr);
    // 5) final projection + bias
    tc_gemm<3><<<dim3(EMBD / 128, BN_ROWS / 128, 1), 256, SMEM_BYTES>>>(nullptr, b_proj, out);
}

// round 11
// speedup vs baseline: 2.0047x; 1.6013x over previous
#include <cuda_runtime.h>
#include <cstdint>

// ---------------------------------------------------------------------------
// Problem constants
// ---------------------------------------------------------------------------
#define EMBD   2048
#define HEADS  8
#define HDIM   256
#define BATCH  2
#define SEQ    2048
#define BN_ROWS (BATCH*SEQ)      // 4096
#define QKV_N  (3*EMBD)          // 6144
#define NBH    (BATCH*HEADS)     // 16

// ---------------------------------------------------------------------------
// Device scratch — all GEMM operands stored PRE-SPLIT as packed bf16 hi/lo:
// word layout per K-pair: uint2{ hi(k),hi(k+1) , lo(k),lo(k+1) }.
// Row of K elements = K/2 uint2 = 4K bytes (same as fp32 row).
// ---------------------------------------------------------------------------
__device__ __align__(1024) uint2 g_px    [(size_t)BN_ROWS * EMBD / 2];   // x split      [4096][1024]
__device__ __align__(1024) uint2 g_pwqkvT[(size_t)QKV_N  * EMBD / 2];    // w_qkv^T split
__device__ __align__(1024) uint2 g_pwprojT[(size_t)EMBD  * EMBD / 2];    // w_proj^T split
__device__ __align__(1024) uint2 g_pq    [(size_t)NBH * SEQ  * HDIM / 2]; // Q split  [bh][n][d/2]
__device__ __align__(1024) uint2 g_pk    [(size_t)NBH * SEQ  * HDIM / 2]; // K split  [bh][n][d/2]
__device__ __align__(1024) uint2 g_pvT   [(size_t)NBH * HDIM * SEQ  / 2]; // V^T split[bh][d][n/2]
__device__ __align__(1024) float g_s     [(size_t)NBH * SEQ  * SEQ];      // logits fp32; softmax re-packs IN PLACE
__device__ __align__(1024) uint2 g_po    [(size_t)BN_ROWS * EMBD / 2];    // O split  [b*n][emb/2]

// ---------------------------------------------------------------------------
// Helpers
// ---------------------------------------------------------------------------
__device__ __forceinline__ void cp_async16(uint32_t s, const void* g) {
    asm volatile("cp.async.cg.shared.global [%0], [%1], 16;" :: "r"(s), "l"(g) : "memory");
}
#define CP_COMMIT() asm volatile("cp.async.commit_group;" ::: "memory")
#define CP_WAIT2()  asm volatile("cp.async.wait_group 2;" ::: "memory")

__device__ __forceinline__ uint32_t smem_u32(const void* p) {
    uint32_t a;
    asm("{ .reg .u64 t; cvta.to.shared.u64 t, %1; cvt.u32.u64 %0, t; }"
        : "=r"(a) : "l"(p));
    return a;
}

// Pack two floats to bf16x2 (word: lo16 = x0, hi16 = x1)
__device__ __forceinline__ uint32_t pack_bf16x2(float x0, float x1) {
    uint32_t w;
    asm("cvt.rn.bf16x2.f32 %0, %1, %2;" : "=r"(w) : "f"(x1), "f"(x0));
    return w;
}

// Split a float pair into bf16 hi-pair word + lo-pair word
__device__ __forceinline__ void split2(float x0, float x1, uint32_t& hw, uint32_t& lw) {
    hw = pack_bf16x2(x0, x1);
    float h0 = __uint_as_float(hw << 16);
    float h1 = __uint_as_float(hw & 0xffff0000u);
    lw = pack_bf16x2(x0 - h0, x1 - h1);
}

// Split a single float into bf16 hi/lo u16
__device__ __forceinline__ void split1(float v, unsigned short& hu, unsigned short& lu) {
    uint32_t hw = pack_bf16x2(v, 0.0f);
    float hf = __uint_as_float(hw << 16);
    uint32_t lw = pack_bf16x2(v - hf, 0.0f);
    hu = (unsigned short)(hw & 0xffffu);
    lu = (unsigned short)(lw & 0xffffu);
}

// bf16 tensor-core mma: D(16x8) += A(16x16) * B(16x8), A row-major, B col-major
__device__ __forceinline__ void mma_bf16(float* c, const uint32_t* a, const uint32_t* b) {
    asm volatile(
        "mma.sync.aligned.m16n8k16.row.col.f32.bf16.bf16.f32 "
        "{%0,%1,%2,%3}, {%4,%5,%6,%7}, {%8,%9}, {%0,%1,%2,%3};"
        : "+f"(c[0]), "+f"(c[1]), "+f"(c[2]), "+f"(c[3])
        : "r"(a[0]), "r"(a[1]), "r"(a[2]), "r"(a[3]), "r"(b[0]), "r"(b[1]));
}

// Load uint2 (hi-word, lo-word) from smem in one LDS.64
__device__ __forceinline__ void lds_v2(uint32_t addr, uint32_t& h, uint32_t& l) {
    asm volatile("ld.shared.v2.b32 {%0, %1}, [%2];" : "=r"(h), "=r"(l) : "r"(addr));
}

// ---------------------------------------------------------------------------
// bf16x3 HMMA GEMM: tile 128x128, BK=32 (2 x k16), 4-stage cp.async,
// 8 warps (4x2), warp tile 32x64, mma m16n8k16, operands pre-split in memory.
// A is packed [M][K/2], B is packed [N][K/2] (B^T => col-major B).
// MODE 0: x @ wqkvT^T     -> scatter split Q / K / V^T (+bias)
// MODE 1: Q @ K^T per bh  -> g_s (fp32)
// MODE 2: P @ V per bh    -> g_po (split, [b,n,h*d] layout)
// MODE 3: o @ wprojT^T    -> out (fp32, +bias)
// ---------------------------------------------------------------------------
#define SROWB   160                     // 128B data + 32B pad (bank-conflict-free LDS.64)
#define TILEB   (128 * SROWB)           // 20480 per operand per stage
#define STGB    (2 * TILEB)             // 40960
#define STAGES  4
#define SMEM_BYTES (STAGES * STGB)      // 163840

template <int MODE>
__global__ __launch_bounds__(256, 1)
void tc_gemm(const float* __restrict__ bias, float* __restrict__ Cout)
{
    constexpr int K     = (MODE == 1) ? HDIM : ((MODE == 2) ? SEQ : EMBD);
    constexpr int ITERS = K / 32;
    constexpr int ROWB  = K * 4;        // packed row bytes

    const int z  = blockIdx.z;
    const int m0 = blockIdx.y * 128;
    const int n0 = blockIdx.x * 128;

    const char* A; const char* B;
    if (MODE == 0)      { A = (const char*)g_px;
                          B = (const char*)g_pwqkvT; }
    else if (MODE == 1) { A = (const char*)(g_pq  + (size_t)z * SEQ * HDIM / 2);
                          B = (const char*)(g_pk  + (size_t)z * SEQ * HDIM / 2); }
    else if (MODE == 2) { A = (const char*)(g_s   + (size_t)z * SEQ * SEQ);     // packed in place
                          B = (const char*)(g_pvT + (size_t)z * HDIM * SEQ / 2); }
    else                { A = (const char*)g_po;
                          B = (const char*)g_pwprojT; }

    extern __shared__ __align__(128) char smem[];
    const uint32_t sb = smem_u32(smem);

    const int tid  = threadIdx.x;
    const int wid  = tid >> 5;
    const int lane = tid & 31;
    const int wm   = wid & 3;          // warp row (4)  -> 32 rows
    const int wn   = wid >> 2;         // warp col (2)  -> 64 cols
    const int grp  = lane >> 2;        // 0..7
    const int qid  = lane & 3;         // 0..3

    const char* Abase = A + (size_t)m0 * ROWB;
    const char* Bbase = B + (size_t)n0 * ROWB;

    auto issue = [&](int it, int s) {
        const uint32_t aS = sb + (uint32_t)s * STGB;
        const uint32_t bS = aS + TILEB;
        const char* gA = Abase + (size_t)it * 128;     // 32 elems = 16 uint2 = 128B
        const char* gB = Bbase + (size_t)it * 128;
        #pragma unroll
        for (int j = 0; j < 4; j++) {
            int u = tid + 256 * j;
            int r = u >> 3, i = u & 7;
            cp_async16(aS + (uint32_t)(r * SROWB + i * 16), gA + (size_t)r * ROWB + i * 16);
        }
        #pragma unroll
        for (int j = 0; j < 4; j++) {
            int u = tid + 256 * j;
            int r = u >> 3, i = u & 7;
            cp_async16(bS + (uint32_t)(r * SROWB + i * 16), gB + (size_t)r * ROWB + i * 16);
        }
        CP_COMMIT();
    };

    float acc[2][8][4];
    #pragma unroll
    for (int mt = 0; mt < 2; mt++)
        #pragma unroll
        for (int nt = 0; nt < 8; nt++)
            #pragma unroll
            for (int e = 0; e < 4; e++) acc[mt][nt][e] = 0.0f;

    issue(0, 0); issue(1, 1); issue(2, 2);

    for (int it = 0; it < ITERS; it++) {
        const int s = it & (STAGES - 1);
        CP_WAIT2();                 // stage 'it' resident (<=2 groups pending)
        __syncthreads();

        if (it + 3 < ITERS) issue(it + 3, (it + 3) & (STAGES - 1));
        else                CP_COMMIT();   // keep group accounting uniform

        const uint32_t aT = sb + (uint32_t)s * STGB;
        const uint32_t bT = aT + TILEB;
        const uint32_t aW = aT + (uint32_t)(wm * 32 + grp) * SROWB + qid * 8;
        const uint32_t bW = bT + (uint32_t)(wn * 64 + grp) * SROWB + qid * 8;

        #pragma unroll
        for (int ko = 0; ko < 2; ko++) {          // two k16 steps per BK=32
            const uint32_t koff = ko * 64;        // 8 pairs * 8B
            uint32_t ah[2][4], al[2][4];
            #pragma unroll
            for (int mt = 0; mt < 2; mt++) {
                const uint32_t p = aW + (uint32_t)(mt * 16) * SROWB + koff;
                lds_v2(p,                  ah[mt][0], al[mt][0]);   // (r,   q)
                lds_v2(p + 8 * SROWB,      ah[mt][1], al[mt][1]);   // (r+8, q)
                lds_v2(p + 32,             ah[mt][2], al[mt][2]);   // (r,   q+4)
                lds_v2(p + 8 * SROWB + 32, ah[mt][3], al[mt][3]);   // (r+8, q+4)
            }
            uint32_t bh[8][2], bl[8][2];
            #pragma unroll
            for (int nt = 0; nt < 8; nt++) {
                const uint32_t p = bW + (uint32_t)(nt * 8) * SROWB + koff;
                lds_v2(p,      bh[nt][0], bl[nt][0]);
                lds_v2(p + 32, bh[nt][1], bl[nt][1]);
            }
            // bf16x3: hi*hi + hi*lo + lo*hi (lo*lo dropped, ~2^-18)
            #pragma unroll
            for (int mt = 0; mt < 2; mt++)
                #pragma unroll
                for (int nt = 0; nt < 8; nt++) {
                    mma_bf16(acc[mt][nt], ah[mt], bh[nt]);
                    mma_bf16(acc[mt][nt], ah[mt], bl[nt]);
                    mma_bf16(acc[mt][nt], al[mt], bh[nt]);
                }
        }
        __syncthreads();            // stage s fully read before refill
    }

    // ---------------- epilogue ----------------
    #pragma unroll
    for (int mt = 0; mt < 2; mt++) {
        #pragma unroll
        for (int half = 0; half < 2; half++) {
            const int gi = m0 + wm * 32 + mt * 16 + grp + half * 8;
            if (MODE == 0) {
                // scatter split Q / K / V^T with bias
                const int bb = gi >> 11;            // batch
                const int ni = gi & (SEQ - 1);      // token
                #pragma unroll
                for (int nt = 0; nt < 8; nt++) {
                    #pragma unroll
                    for (int e = 0; e < 2; e++) {
                        const int gj = n0 + wn * 64 + nt * 8 + qid * 2 + e;
                        float val = acc[mt][nt][half * 2 + e] + bias[gj];
                        unsigned short hu, lu;
                        split1(val, hu, lu);
                        const int which = gj % 3;
                        const int tt    = gj / 3;
                        const int h     = tt >> 8;
                        const int d     = tt & (HDIM - 1);
                        const int bh    = (bb << 3) + h;
                        if (which == 2) {
                            unsigned short* vb = (unsigned short*)g_pvT;
                            size_t w = ((size_t)bh * HDIM + d) * (SEQ / 2) + (ni >> 1);
                            vb[w * 4 + (ni & 1)]     = hu;
                            vb[w * 4 + 2 + (ni & 1)] = lu;
                        } else {
                            unsigned short* qb = (unsigned short*)((which == 0) ? g_pq : g_pk);
                            size_t w = ((size_t)bh * SEQ + ni) * (HDIM / 2) + (d >> 1);
                            qb[w * 4 + (d & 1)]     = hu;
                            qb[w * 4 + 2 + (d & 1)] = lu;
                        }
                    }
                }
            } else if (MODE == 1) {
                // fp32 logits
                float* crow = g_s + (size_t)z * SEQ * SEQ
                            + (size_t)gi * SEQ + n0 + wn * 64 + qid * 2;
                #pragma unroll
                for (int nt = 0; nt < 8; nt++) {
                    float2 v;
                    v.x = acc[mt][nt][half * 2 + 0];
                    v.y = acc[mt][nt][half * 2 + 1];
                    *(float2*)(crow + nt * 8) = v;
                }
            } else if (MODE == 2) {
                // split O, [b*n][emb/2] packed
                const size_t orow = (size_t)(z >> 3) * SEQ + gi;
                #pragma unroll
                for (int nt = 0; nt < 8; nt++) {
                    const int ec = (z & 7) * HDIM + n0 + wn * 64 + nt * 8 + qid * 2;
                    uint32_t hw, lw;
                    split2(acc[mt][nt][half * 2 + 0], acc[mt][nt][half * 2 + 1], hw, lw);
                    g_po[orow * (EMBD / 2) + (ec >> 1)] = make_uint2(hw, lw);
                }
            } else {
                // fp32 output + bias
                float* crow = Cout + (size_t)gi * EMBD + n0 + wn * 64 + qid * 2;
                #pragma unroll
                for (int nt = 0; nt < 8; nt++) {
                    const int gj = n0 + wn * 64 + nt * 8 + qid * 2;
                    float2 v;
                    v.x = acc[mt][nt][half * 2 + 0] + bias[gj + 0];
                    v.y = acc[mt][nt][half * 2 + 1] + bias[gj + 1];
                    *(float2*)(crow + nt * 8) = v;
                }
            }
        }
    }
}

// ---------------------------------------------------------------------------
// Transpose + split weights: in fp32 [K][N] -> out packed [N][K/2]
// Input tile: rows 2*j0 .. 2*j0+63 (64 rows), cols n0 .. n0+31.
// Output tile: 32 cols (n) x 32 K-pairs (x) => 1024 uint2, 4 per thread.
// ---------------------------------------------------------------------------
__global__ __launch_bounds__(256)
void transpose_pack_k(const float* __restrict__ in, uint2* __restrict__ out,
                      int Kdim, int N)
{
    __shared__ float t[64][33];
    const int j0 = blockIdx.y * 32;     // output pair index base
    const int n0 = blockIdx.x * 32;
    const int x  = threadIdx.x & 31;
    const int y  = threadIdx.x >> 5;    // 0..7
    #pragma unroll
    for (int i = 0; i < 8; i++) {
        const int r = y + 8 * i;        // 0..63
        t[r][x] = in[(size_t)(2 * j0 + r) * N + n0 + x];
    }
    __syncthreads();
    #pragma unroll
    for (int i = 0; i < 4; i++) {       // FIX (was 8): 1024 outputs / 256 thr = 4
        const int n = y + 8 * i;        // 0..31
        uint32_t hw, lw;
        split2(t[2 * x][n], t[2 * x + 1][n], hw, lw);
        out[(size_t)(n0 + n) * (Kdim / 2) + j0 + x] = make_uint2(hw, lw);
    }
}

// Split-copy of x: fp32 pairs -> packed uint2
__global__ __launch_bounds__(256)
void splitx_k(const float2* __restrict__ in, uint2* __restrict__ out, int np)
{
    int i = blockIdx.x * blockDim.x + threadIdx.x;
    if (i < np) {
        float2 v = in[i];
        uint32_t hw, lw;
        split2(v.x, v.y, hw, lw);
        out[i] = make_uint2(hw, lw);
    }
}

// ---------------------------------------------------------------------------
// Row softmax over g_s, folds post-softmax 1/sqrt(EMB), re-packs the row
// IN PLACE as split bf16 pairs (for the P@V GEMM).
// ---------------------------------------------------------------------------
__global__ __launch_bounds__(256)
void softmax_k()
{
    constexpr float INV_SCALE = 0.02209708691207961f;   // 1/sqrt(2048)
    float* p = g_s + (size_t)blockIdx.x * SEQ;
    const int t = threadIdx.x, w = t >> 5, l = t & 31;

    float2 v[4];
    float m = -3.0e38f;
    #pragma unroll
    for (int u = 0; u < 4; u++) {
        v[u] = ((const float2*)p)[t + 256 * u];
        m = fmaxf(m, fmaxf(v[u].x, v[u].y));
    }
    #pragma unroll
    for (int o = 16; o > 0; o >>= 1) m = fmaxf(m, __shfl_xor_sync(~0u, m, o));

    __shared__ float redm[8], reds[8];
    if (l == 0) redm[w] = m;
    __syncthreads();
    m = redm[0];
    #pragma unroll
    for (int i = 1; i < 8; i++) m = fmaxf(m, redm[i]);

    float s = 0.0f;
    #pragma unroll
    for (int u = 0; u < 4; u++) {
        v[u].x = __expf(v[u].x - m);
        v[u].y = __expf(v[u].y - m);
        s += v[u].x + v[u].y;
    }
    #pragma unroll
    for (int o = 16; o > 0; o >>= 1) s += __shfl_xor_sync(~0u, s, o);
    if (l == 0) reds[w] = s;
    __syncthreads();
    s = reds[0];
    #pragma unroll
    for (int i = 1; i < 8; i++) s += reds[i];

    const float r = INV_SCALE / s;
    uint2* q = (uint2*)p;               // in-place re-pack (each word owned by one thread)
    #pragma unroll
    for (int u = 0; u < 4; u++) {
        uint32_t hw, lw;
        split2(v[u].x * r, v[u].y * r, hw, lw);
        q[t + 256 * u] = make_uint2(hw, lw);
    }
}

// ---------------------------------------------------------------------------
extern "C" void kernel_launch(void* const* d_in, const int* in_sizes, int n_in,
                              void* d_out, int out_size)
{
    const float* x      = (const float*)d_in[0];
    const float* w_qkv  = (const float*)d_in[1];
    const float* b_qkv  = (const float*)d_in[2];
    const float* w_proj = (const float*)d_in[3];
    const float* b_proj = (const float*)d_in[4];
    float*       out    = (float*)d_out;

    cudaFuncSetAttribute(tc_gemm<0>, cudaFuncAttributeMaxDynamicSharedMemorySize, SMEM_BYTES);
    cudaFuncSetAttribute(tc_gemm<1>, cudaFuncAttributeMaxDynamicSharedMemorySize, SMEM_BYTES);
    cudaFuncSetAttribute(tc_gemm<2>, cudaFuncAttributeMaxDynamicSharedMemorySize, SMEM_BYTES);
    cudaFuncSetAttribute(tc_gemm<3>, cudaFuncAttributeMaxDynamicSharedMemorySize, SMEM_BYTES);

    uint2* gpx; uint2* gwq; uint2* gwp;
    cudaGetSymbolAddress((void**)&gpx, g_px);
    cudaGetSymbolAddress((void**)&gwq, g_pwqkvT);
    cudaGetSymbolAddress((void**)&gwp, g_pwprojT);

    // 0) split x; transpose+split weights
    const int np = (BN_ROWS * EMBD) / 2;
    splitx_k<<<(np + 255) / 256, 256>>>((const float2*)x, gpx, np);
    transpose_pack_k<<<dim3(QKV_N / 32, EMBD / 64), 256>>>(w_qkv,  gwq, EMBD, QKV_N);
    transpose_pack_k<<<dim3(EMBD  / 32, EMBD / 64), 256>>>(w_proj, gwp, EMBD, EMBD);

    // 1) QKV projection + de-interleave into split Q / K / V^T
    tc_gemm<0><<<dim3(QKV_N / 128, BN_ROWS / 128, 1), 256, SMEM_BYTES>>>(b_qkv, nullptr);
    // 2) scores S = Q @ K^T per bh (fp32 out)
    tc_gemm<1><<<dim3(SEQ / 128, SEQ / 128, NBH), 256, SMEM_BYTES>>>(nullptr, nullptr);
    // 3) softmax (folds 1/sqrt(EMB)) + in-place split re-pack
    softmax_k<<<NBH * SEQ, 256>>>();
    // 4) O = P @ V per bh -> split [b, n, h*d]
    tc_gemm<2><<<dim3(HDIM / 128, SEQ / 128, NBH), 256, SMEM_BYTES>>>(nullptr, nullptr);
    // 5) final projection + bias (fp32 out)
    tc_gemm<3><<<dim3(EMBD / 128, BN_ROWS / 128, 1), 256, SMEM_BYTES>>>(b_proj, out);
}

// round 12
// speedup vs baseline: 2.0396x; 1.0174x over previous
#include <cuda_runtime.h>
#include <cstdint>

// ---------------------------------------------------------------------------
// Problem constants
// ---------------------------------------------------------------------------
#define EMBD   2048
#define HEADS  8
#define HDIM   256
#define BATCH  2
#define SEQ    2048
#define BN_ROWS (BATCH*SEQ)      // 4096
#define QKV_N  (3*EMBD)          // 6144
#define NBH    (BATCH*HEADS)     // 16

// ---------------------------------------------------------------------------
// Device scratch — all GEMM operands stored PRE-SPLIT as packed bf16 hi/lo:
// word layout per K-pair: uint2{ hi(k),hi(k+1) , lo(k),lo(k+1) }.
// Row of K elements = K/2 uint2 = 4K bytes (same as fp32 row).
// ---------------------------------------------------------------------------
__device__ __align__(1024) uint2 g_px    [(size_t)BN_ROWS * EMBD / 2];   // x split      [4096][1024]
__device__ __align__(1024) uint2 g_pwqkvT[(size_t)QKV_N  * EMBD / 2];    // w_qkv^T split
__device__ __align__(1024) uint2 g_pwprojT[(size_t)EMBD  * EMBD / 2];    // w_proj^T split
__device__ __align__(1024) uint2 g_pq    [(size_t)NBH * SEQ  * HDIM / 2]; // Q split  [bh][n][d/2]
__device__ __align__(1024) uint2 g_pk    [(size_t)NBH * SEQ  * HDIM / 2]; // K split  [bh][n][d/2]
__device__ __align__(1024) uint2 g_pvT   [(size_t)NBH * HDIM * SEQ  / 2]; // V^T split[bh][d][n/2]
__device__ __align__(1024) float g_s     [(size_t)NBH * SEQ  * SEQ];      // logits fp32; softmax re-packs IN PLACE
__device__ __align__(1024) uint2 g_po    [(size_t)BN_ROWS * EMBD / 2];    // O split  [b*n][emb/2]

// ---------------------------------------------------------------------------
// Helpers
// ---------------------------------------------------------------------------
__device__ __forceinline__ void cp_async16(uint32_t s, const void* g) {
    asm volatile("cp.async.cg.shared.global [%0], [%1], 16;" :: "r"(s), "l"(g) : "memory");
}
#define CP_COMMIT() asm volatile("cp.async.commit_group;" ::: "memory")
#define CP_WAIT3()  asm volatile("cp.async.wait_group 3;" ::: "memory")

__device__ __forceinline__ uint32_t smem_u32(const void* p) {
    uint32_t a;
    asm("{ .reg .u64 t; cvta.to.shared.u64 t, %1; cvt.u32.u64 %0, t; }"
        : "=r"(a) : "l"(p));
    return a;
}

// Pack two floats to bf16x2 (word: lo16 = x0, hi16 = x1)
__device__ __forceinline__ uint32_t pack_bf16x2(float x0, float x1) {
    uint32_t w;
    asm("cvt.rn.bf16x2.f32 %0, %1, %2;" : "=r"(w) : "f"(x1), "f"(x0));
    return w;
}

// Split a float pair into bf16 hi-pair word + lo-pair word
__device__ __forceinline__ void split2(float x0, float x1, uint32_t& hw, uint32_t& lw) {
    hw = pack_bf16x2(x0, x1);
    float h0 = __uint_as_float(hw << 16);
    float h1 = __uint_as_float(hw & 0xffff0000u);
    lw = pack_bf16x2(x0 - h0, x1 - h1);
}

// Split a single float into bf16 hi/lo u16
__device__ __forceinline__ void split1(float v, unsigned short& hu, unsigned short& lu) {
    uint32_t hw = pack_bf16x2(v, 0.0f);
    float hf = __uint_as_float(hw << 16);
    uint32_t lw = pack_bf16x2(v - hf, 0.0f);
    hu = (unsigned short)(hw & 0xffffu);
    lu = (unsigned short)(lw & 0xffffu);
}

// bf16 tensor-core mma: D(16x8) += A(16x16) * B(16x8), A row-major, B col-major
__device__ __forceinline__ void mma_bf16(float* c, const uint32_t* a, const uint32_t* b) {
    asm volatile(
        "mma.sync.aligned.m16n8k16.row.col.f32.bf16.bf16.f32 "
        "{%0,%1,%2,%3}, {%4,%5,%6,%7}, {%8,%9}, {%0,%1,%2,%3};"
        : "+f"(c[0]), "+f"(c[1]), "+f"(c[2]), "+f"(c[3])
        : "r"(a[0]), "r"(a[1]), "r"(a[2]), "r"(a[3]), "r"(b[0]), "r"(b[1]));
}

// Load uint2 (hi-word, lo-word) from smem in one LDS.64
__device__ __forceinline__ void lds_v2(uint32_t addr, uint32_t& h, uint32_t& l) {
    asm volatile("ld.shared.v2.b32 {%0, %1}, [%2];" : "=r"(h), "=r"(l) : "r"(addr));
}

// ---------------------------------------------------------------------------
// bf16x3 HMMA GEMM: tile 128x128, BK=32 (2 x k16), 5-stage cp.async,
// 8 warps (4x2), warp tile 32x64, mma m16n8k16, operands pre-split in memory.
// Mainloop: ONE barrier per iter; all 48 frag LDS issued before the 96 MMAs.
// MODE 0: x @ wqkvT^T     -> scatter split Q / K / V^T (+bias)
// MODE 1: Q @ K^T per bh  -> g_s (fp32)
// MODE 2: P @ V per bh    -> g_po (split, [b,n,h*d] layout)
// MODE 3: o @ wprojT^T    -> out (fp32, +bias)
// ---------------------------------------------------------------------------
#define SROWB   160                     // 128B data + 32B pad (bank-conflict-free LDS.64)
#define TILEB   (128 * SROWB)           // 20480 per operand per stage
#define STGB    (2 * TILEB)             // 40960
#define STAGES  5
#define SMEM_BYTES (STAGES * STGB)      // 204800

template <int MODE>
__global__ __launch_bounds__(256, 1)
void tc_gemm(const float* __restrict__ bias, float* __restrict__ Cout)
{
    constexpr int K     = (MODE == 1) ? HDIM : ((MODE == 2) ? SEQ : EMBD);
    constexpr int ITERS = K / 32;
    constexpr int ROWB  = K * 4;        // packed row bytes

    const int z  = blockIdx.z;
    const int m0 = blockIdx.y * 128;
    const int n0 = blockIdx.x * 128;

    const char* A; const char* B;
    if (MODE == 0)      { A = (const char*)g_px;
                          B = (const char*)g_pwqkvT; }
    else if (MODE == 1) { A = (const char*)(g_pq  + (size_t)z * SEQ * HDIM / 2);
                          B = (const char*)(g_pk  + (size_t)z * SEQ * HDIM / 2); }
    else if (MODE == 2) { A = (const char*)(g_s   + (size_t)z * SEQ * SEQ);     // packed in place
                          B = (const char*)(g_pvT + (size_t)z * HDIM * SEQ / 2); }
    else                { A = (const char*)g_po;
                          B = (const char*)g_pwprojT; }

    extern __shared__ __align__(128) char smem[];
    const uint32_t sb = smem_u32(smem);

    const int tid  = threadIdx.x;
    const int wid  = tid >> 5;
    const int lane = tid & 31;
    const int wm   = wid & 3;          // warp row (4)  -> 32 rows
    const int wn   = wid >> 2;         // warp col (2)  -> 64 cols
    const int grp  = lane >> 2;        // 0..7
    const int qid  = lane & 3;         // 0..3

    const char* Abase = A + (size_t)m0 * ROWB;
    const char* Bbase = B + (size_t)n0 * ROWB;

    auto issue = [&](int it, int s) {
        const uint32_t aS = sb + (uint32_t)s * STGB;
        const uint32_t bS = aS + TILEB;
        const char* gA = Abase + (size_t)it * 128;     // 32 elems = 16 uint2 = 128B
        const char* gB = Bbase + (size_t)it * 128;
        #pragma unroll
        for (int j = 0; j < 4; j++) {
            int u = tid + 256 * j;
            int r = u >> 3, i = u & 7;
            cp_async16(aS + (uint32_t)(r * SROWB + i * 16), gA + (size_t)r * ROWB + i * 16);
        }
        #pragma unroll
        for (int j = 0; j < 4; j++) {
            int u = tid + 256 * j;
            int r = u >> 3, i = u & 7;
            cp_async16(bS + (uint32_t)(r * SROWB + i * 16), gB + (size_t)r * ROWB + i * 16);
        }
        CP_COMMIT();
    };

    float acc[2][8][4];
    #pragma unroll
    for (int mt = 0; mt < 2; mt++)
        #pragma unroll
        for (int nt = 0; nt < 8; nt++)
            #pragma unroll
            for (int e = 0; e < 4; e++) acc[mt][nt][e] = 0.0f;

    issue(0, 0); issue(1, 1); issue(2, 2); issue(3, 3);

    int sc = 0;                 // stage being read this iter
    int si = 4 % STAGES;        // stage to fill next

    for (int it = 0; it < ITERS; it++) {
        CP_WAIT3();                 // stage 'it' group complete (<=3 pending)
        __syncthreads();            // also: all warps done reading stage 'si'

        if (it + 4 < ITERS) issue(it + 4, si);
        else                CP_COMMIT();   // keep group accounting uniform
        if (++si == STAGES) si = 0;

        const uint32_t aT = sb + (uint32_t)sc * STGB;
        const uint32_t bT = aT + TILEB;
        const uint32_t aW = aT + (uint32_t)(wm * 32 + grp) * SROWB + qid * 8;
        const uint32_t bW = bT + (uint32_t)(wn * 64 + grp) * SROWB + qid * 8;
        if (++sc == STAGES) sc = 0;

        // ---- preload ALL fragments for both k16 steps (48 LDS.64) ----
        uint32_t ah[2][2][4], al[2][2][4];     // [ko][mt][..]
        uint32_t bh[2][8][2], bl[2][8][2];     // [ko][nt][..]
        #pragma unroll
        for (int ko = 0; ko < 2; ko++) {
            const uint32_t koff = ko * 64;     // 8 pairs * 8B
            #pragma unroll
            for (int mt = 0; mt < 2; mt++) {
                const uint32_t p = aW + (uint32_t)(mt * 16) * SROWB + koff;
                lds_v2(p,                  ah[ko][mt][0], al[ko][mt][0]);
                lds_v2(p + 8 * SROWB,      ah[ko][mt][1], al[ko][mt][1]);
                lds_v2(p + 32,             ah[ko][mt][2], al[ko][mt][2]);
                lds_v2(p + 8 * SROWB + 32, ah[ko][mt][3], al[ko][mt][3]);
            }
            #pragma unroll
            for (int nt = 0; nt < 8; nt++) {
                const uint32_t p = bW + (uint32_t)(nt * 8) * SROWB + koff;
                lds_v2(p,      bh[ko][nt][0], bl[ko][nt][0]);
                lds_v2(p + 32, bh[ko][nt][1], bl[ko][nt][1]);
            }
        }
        // ---- 96 MMAs: bf16x3 = hi*hi + hi*lo + lo*hi ----
        #pragma unroll
        for (int ko = 0; ko < 2; ko++)
            #pragma unroll
            for (int mt = 0; mt < 2; mt++)
                #pragma unroll
                for (int nt = 0; nt < 8; nt++) {
                    mma_bf16(acc[mt][nt], ah[ko][mt], bh[ko][nt]);
                    mma_bf16(acc[mt][nt], ah[ko][mt], bl[ko][nt]);
                    mma_bf16(acc[mt][nt], al[ko][mt], bh[ko][nt]);
                }
        // no trailing barrier: next iter's top barrier orders stage reuse
    }

    // ---------------- epilogue ----------------
    #pragma unroll
    for (int mt = 0; mt < 2; mt++) {
        #pragma unroll
        for (int half = 0; half < 2; half++) {
            const int gi = m0 + wm * 32 + mt * 16 + grp + half * 8;
            if (MODE == 0) {
                // scatter split Q / K / V^T with bias
                const int bb = gi >> 11;            // batch
                const int ni = gi & (SEQ - 1);      // token
                #pragma unroll
                for (int nt = 0; nt < 8; nt++) {
                    #pragma unroll
                    for (int e = 0; e < 2; e++) {
                        const int gj = n0 + wn * 64 + nt * 8 + qid * 2 + e;
                        float val = acc[mt][nt][half * 2 + e] + bias[gj];
                        unsigned short hu, lu;
                        split1(val, hu, lu);
                        const int which = gj % 3;
                        const int tt    = gj / 3;
                        const int h     = tt >> 8;
                        const int d     = tt & (HDIM - 1);
                        const int bh    = (bb << 3) + h;
                        if (which == 2) {
                            unsigned short* vb = (unsigned short*)g_pvT;
                            size_t w = ((size_t)bh * HDIM + d) * (SEQ / 2) + (ni >> 1);
                            vb[w * 4 + (ni & 1)]     = hu;
                            vb[w * 4 + 2 + (ni & 1)] = lu;
                        } else {
                            unsigned short* qb = (unsigned short*)((which == 0) ? g_pq : g_pk);
                            size_t w = ((size_t)bh * SEQ + ni) * (HDIM / 2) + (d >> 1);
                            qb[w * 4 + (d & 1)]     = hu;
                            qb[w * 4 + 2 + (d & 1)] = lu;
                        }
                    }
                }
            } else if (MODE == 1) {
                // fp32 logits
                float* crow = g_s + (size_t)z * SEQ * SEQ
                            + (size_t)gi * SEQ + n0 + wn * 64 + qid * 2;
                #pragma unroll
                for (int nt = 0; nt < 8; nt++) {
                    float2 v;
                    v.x = acc[mt][nt][half * 2 + 0];
                    v.y = acc[mt][nt][half * 2 + 1];
                    *(float2*)(crow + nt * 8) = v;
                }
            } else if (MODE == 2) {
                // split O, [b*n][emb/2] packed
                const size_t orow = (size_t)(z >> 3) * SEQ + gi;
                #pragma unroll
                for (int nt = 0; nt < 8; nt++) {
                    const int ec = (z & 7) * HDIM + n0 + wn * 64 + nt * 8 + qid * 2;
                    uint32_t hw, lw;
                    split2(acc[mt][nt][half * 2 + 0], acc[mt][nt][half * 2 + 1], hw, lw);
                    g_po[orow * (EMBD / 2) + (ec >> 1)] = make_uint2(hw, lw);
                }
            } else {
                // fp32 output + bias
                float* crow = Cout + (size_t)gi * EMBD + n0 + wn * 64 + qid * 2;
                #pragma unroll
                for (int nt = 0; nt < 8; nt++) {
                    const int gj = n0 + wn * 64 + nt * 8 + qid * 2;
                    float2 v;
                    v.x = acc[mt][nt][half * 2 + 0] + bias[gj + 0];
                    v.y = acc[mt][nt][half * 2 + 1] + bias[gj + 1];
                    *(float2*)(crow + nt * 8) = v;
                }
            }
        }
    }
}

// ---------------------------------------------------------------------------
// Transpose + split weights: in fp32 [K][N] -> out packed [N][K/2]
// Input tile: rows 2*j0 .. 2*j0+63 (64 rows), cols n0 .. n0+31.
// Output tile: 32 cols (n) x 32 K-pairs (x) => 1024 uint2, 4 per thread.
// ---------------------------------------------------------------------------
__global__ __launch_bounds__(256)
void transpose_pack_k(const float* __restrict__ in, uint2* __restrict__ out,
                      int Kdim, int N)
{
    __shared__ float t[64][33];
    const int j0 = blockIdx.y * 32;     // output pair index base
    const int n0 = blockIdx.x * 32;
    const int x  = threadIdx.x & 31;
    const int y  = threadIdx.x >> 5;    // 0..7
    #pragma unroll
    for (int i = 0; i < 8; i++) {
        const int r = y + 8 * i;        // 0..63
        t[r][x] = in[(size_t)(2 * j0 + r) * N + n0 + x];
    }
    __syncthreads();
    #pragma unroll
    for (int i = 0; i < 4; i++) {       // 1024 outputs / 256 thr = 4
        const int n = y + 8 * i;        // 0..31
        uint32_t hw, lw;
        split2(t[2 * x][n], t[2 * x + 1][n], hw, lw);
        out[(size_t)(n0 + n) * (Kdim / 2) + j0 + x] = make_uint2(hw, lw);
    }
}

// Split-copy of x: fp32 pairs -> packed uint2
__global__ __launch_bounds__(256)
void splitx_k(const float2* __restrict__ in, uint2* __restrict__ out, int np)
{
    int i = blockIdx.x * blockDim.x + threadIdx.x;
    if (i < np) {
        float2 v = in[i];
        uint32_t hw, lw;
        split2(v.x, v.y, hw, lw);
        out[i] = make_uint2(hw, lw);
    }
}

// ---------------------------------------------------------------------------
// Row softmax over g_s, folds post-softmax 1/sqrt(EMB), re-packs the row
// IN PLACE as split bf16 pairs (for the P@V GEMM).
// ---------------------------------------------------------------------------
__global__ __launch_bounds__(256)
void softmax_k()
{
    constexpr float INV_SCALE = 0.02209708691207961f;   // 1/sqrt(2048)
    float* p = g_s + (size_t)blockIdx.x * SEQ;
    const int t = threadIdx.x, w = t >> 5, l = t & 31;

    float2 v[4];
    float m = -3.0e38f;
    #pragma unroll
    for (int u = 0; u < 4; u++) {
        v[u] = ((const float2*)p)[t + 256 * u];
        m = fmaxf(m, fmaxf(v[u].x, v[u].y));
    }
    #pragma unroll
    for (int o = 16; o > 0; o >>= 1) m = fmaxf(m, __shfl_xor_sync(~0u, m, o));

    __shared__ float redm[8], reds[8];
    if (l == 0) redm[w] = m;
    __syncthreads();
    m = redm[0];
    #pragma unroll
    for (int i = 1; i < 8; i++) m = fmaxf(m, redm[i]);

    float s = 0.0f;
    #pragma unroll
    for (int u = 0; u < 4; u++) {
        v[u].x = __expf(v[u].x - m);
        v[u].y = __expf(v[u].y - m);
        s += v[u].x + v[u].y;
    }
    #pragma unroll
    for (int o = 16; o > 0; o >>= 1) s += __shfl_xor_sync(~0u, s, o);
    if (l == 0) reds[w] = s;
    __syncthreads();
    s = reds[0];
    #pragma unroll
    for (int i = 1; i < 8; i++) s += reds[i];

    const float r = INV_SCALE / s;
    uint2* q = (uint2*)p;               // in-place re-pack (each word owned by one thread)
    #pragma unroll
    for (int u = 0; u < 4; u++) {
        uint32_t hw, lw;
        split2(v[u].x * r, v[u].y * r, hw, lw);
        q[t + 256 * u] = make_uint2(hw, lw);
    }
}

// ---------------------------------------------------------------------------
extern "C" void kernel_launch(void* const* d_in, const int* in_sizes, int n_in,
                              void* d_out, int out_size)
{
    const float* x      = (const float*)d_in[0];
    const float* w_qkv  = (const float*)d_in[1];
    const float* b_qkv  = (const float*)d_in[2];
    const float* w_proj = (const float*)d_in[3];
    const float* b_proj = (const float*)d_in[4];
    float*       out    = (float*)d_out;

    cudaFuncSetAttribute(tc_gemm<0>, cudaFuncAttributeMaxDynamicSharedMemorySize, SMEM_BYTES);
    cudaFuncSetAttribute(tc_gemm<1>, cudaFuncAttributeMaxDynamicSharedMemorySize, SMEM_BYTES);
    cudaFuncSetAttribute(tc_gemm<2>, cudaFuncAttributeMaxDynamicSharedMemorySize, SMEM_BYTES);
    cudaFuncSetAttribute(tc_gemm<3>, cudaFuncAttributeMaxDynamicSharedMemorySize, SMEM_BYTES);

    uint2* gpx; uint2* gwq; uint2* gwp;
    cudaGetSymbolAddress((void**)&gpx, g_px);
    cudaGetSymbolAddress((void**)&gwq, g_pwqkvT);
    cudaGetSymbolAddress((void**)&gwp, g_pwprojT);

    // 0) split x; transpose+split weights
    const int np = (BN_ROWS * EMBD) / 2;
    splitx_k<<<(np + 255) / 256, 256>>>((const float2*)x, gpx, np);
    transpose_pack_k<<<dim3(QKV_N / 32, EMBD / 64), 256>>>(w_qkv,  gwq, EMBD, QKV_N);
    transpose_pack_k<<<dim3(EMBD  / 32, EMBD / 64), 256>>>(w_proj, gwp, EMBD, EMBD);

    // 1) QKV projection + de-interleave into split Q / K / V^T
    tc_gemm<0><<<dim3(QKV_N / 128, BN_ROWS / 128, 1), 256, SMEM_BYTES>>>(b_qkv, nullptr);
    // 2) scores S = Q @ K^T per bh (fp32 out)
    tc_gemm<1><<<dim3(SEQ / 128, SEQ / 128, NBH), 256, SMEM_BYTES>>>(nullptr, nullptr);
    // 3) softmax (folds 1/sqrt(EMB)) + in-place split re-pack
    softmax_k<<<NBH * SEQ, 256>>>();
    // 4) O = P @ V per bh -> split [b, n, h*d]
    tc_gemm<2><<<dim3(HDIM / 128, SEQ / 128, NBH), 256, SMEM_BYTES>>>(nullptr, nullptr);
    // 5) final projection + bias (fp32 out)
    tc_gemm<3><<<dim3(EMBD / 128, BN_ROWS / 128, 1), 256, SMEM_BYTES>>>(b_proj, out);
}